// round 8
// baseline (speedup 1.0000x reference)
#include <cuda_runtime.h>
#include <cuda_fp16.h>
#include <cuda_bf16.h>
#include <math.h>
#include <stdint.h>

// Problem constants
#define B_SZ   4
#define SEQ    2048
#define DMODEL 1024
#define NSTATE 16
#define MROWS  (B_SZ*SEQ)        // 8192
#define NCHUNK 32
#define CLEN   64                // NCHUNK*CLEN == SEQ

// ---------------- device scratch (no allocations allowed) ----------------
__device__ __align__(16) float g_delta[MROWS*DMODEL];
__device__ __align__(16) float g_Bm[MROWS*NSTATE];
__device__ __align__(16) float g_Cm[MROWS*NSTATE];
__device__ __align__(16) float g_A2[DMODEL*NSTATE];
__device__ __align__(16) float g_P [B_SZ*NCHUNK*DMODEL*NSTATE];
__device__ __align__(16) float g_E [B_SZ*NCHUNK*DMODEL*NSTATE];
__device__ __align__(16) float g_hin[B_SZ*NCHUNK*DMODEL*NSTATE];
__device__ __align__(16) __half g_Xh[MROWS*DMODEL];    // fp16 X      16 MB
__device__ __align__(16) __half g_Wh[DMODEL*DMODEL];   // fp16 Wd     2 MB

// ---------------- helpers ----------------
__device__ __forceinline__ float ex2(float x) {
    float r;
    asm("ex2.approx.ftz.f32 %0, %1;" : "=f"(r) : "f"(x));
    return r;
}
__device__ __forceinline__ float softplus_f(float z) {
    return fmaxf(z, 0.0f) + log1pf(__expf(-fabsf(z)));
}
__device__ __forceinline__ uint32_t smem_u32(const void* p) {
    uint32_t a;
    asm("{ .reg .u64 t; cvta.to.shared.u64 t, %1; cvt.u32.u64 %0, t; }"
        : "=r"(a) : "l"(p));
    return a;
}
__device__ __forceinline__ void cp_async16(uint32_t dst, const void* src) {
    asm volatile("cp.async.cg.shared.global [%0], [%1], 16;" :: "r"(dst), "l"(src));
}
#define CP_COMMIT() asm volatile("cp.async.commit_group;" ::: "memory")
#define CP_WAIT(n)  asm volatile("cp.async.wait_group %0;" :: "n"(n) : "memory")

__device__ __forceinline__ void ldsm_x4(
    uint32_t& r0, uint32_t& r1, uint32_t& r2, uint32_t& r3, uint32_t addr)
{
    asm volatile("ldmatrix.sync.aligned.m8n8.x4.shared.b16 {%0,%1,%2,%3}, [%4];"
                 : "=r"(r0), "=r"(r1), "=r"(r2), "=r"(r3) : "r"(addr));
}
__device__ __forceinline__ void ldsm_x4_t(
    uint32_t& r0, uint32_t& r1, uint32_t& r2, uint32_t& r3, uint32_t addr)
{
    asm volatile("ldmatrix.sync.aligned.m8n8.x4.trans.shared.b16 {%0,%1,%2,%3}, [%4];"
                 : "=r"(r0), "=r"(r1), "=r"(r2), "=r"(r3) : "r"(addr));
}
__device__ __forceinline__ void mma_f16(
    float& d0, float& d1, float& d2, float& d3,
    uint32_t a0, uint32_t a1, uint32_t a2, uint32_t a3,
    uint32_t b0, uint32_t b1)
{
    asm volatile(
        "mma.sync.aligned.m16n8k16.row.col.f32.f16.f16.f32 "
        "{%0,%1,%2,%3}, {%4,%5,%6,%7}, {%8,%9}, {%0,%1,%2,%3};"
        : "+f"(d0), "+f"(d1), "+f"(d2), "+f"(d3)
        : "r"(a0), "r"(a1), "r"(a2), "r"(a3), "r"(b0), "r"(b1));
}

// ---------------- kernel 0: A2 = -exp(A_log) * log2(e) ----------------
__global__ void prep_A2_kernel(const float* __restrict__ A_log) {
    int i = blockIdx.x * 256 + threadIdx.x;
    if (i < DMODEL*NSTATE)
        g_A2[i] = -__expf(A_log[i]) * 1.44269504088896f;
}

// ---------------- conversion: fp32 -> fp16 ----------------
__global__ __launch_bounds__(256) void convert_f16_kernel(
    const float* __restrict__ src, __half* __restrict__ dst)
{
    int i4 = blockIdx.x * 256 + threadIdx.x;
    float4 v = ((const float4*)src)[i4];
    __half2 h0 = __floats2half2_rn(v.x, v.y);
    __half2 h1 = __floats2half2_rn(v.z, v.w);
    ((__half2*)dst)[i4*2]   = h0;
    ((__half2*)dst)[i4*2+1] = h1;
}

// ---------------- kernel 1: delta = softplus(x @ Wd + bd), fp16 mma ------
// 128x128 block, 256 threads, 2 CTAs/SM, warp tile 64x32, cp.async dbuf.
// A smem: [128 m][32 k] half, 64B/row, swz c^=((row>>1)&3)
// B smem: [32 k][128 n] half, 256B/row, swz c^=(k&7) (c in 0..15)
#define GBM 128
#define GBN 128
#define GBK 32
#define ASZ 8192      // bytes per A buffer
#define BSZ 8192      // bytes per B buffer
#define GEMM_SMEM (2*(ASZ+BSZ))   // 32768

__global__ __launch_bounds__(256, 2) void gemm_f16_softplus(
    const float* __restrict__ bias)
{
    const int K = DMODEL, N = DMODEL;
    extern __shared__ __align__(128) char smem[];
    uint32_t sA_u = smem_u32(smem);              // 2 x 8KB
    uint32_t sB_u = sA_u + 2*ASZ;                // 2 x 8KB

    int tid  = threadIdx.x;
    int wid  = tid >> 5, lane = tid & 31;
    int g    = lane >> 2, tg = lane & 3;
    int brow = blockIdx.y * GBM;
    int bcol = blockIdx.x * GBN;

    // cp.async mappings (16B chunks)
    // A: 512 chunks -> 2/thread. row = ci>>2, c = ci&3
    int a_r0 = tid >> 2,          a_c0 = tid & 3;
    int a_r1 = (tid + 256) >> 2;
    const __half* Ag0 = g_Xh + (size_t)(brow + a_r0) * K + a_c0 * 8;
    const __half* Ag1 = g_Xh + (size_t)(brow + a_r1) * K + a_c0 * 8;
    uint32_t dA0 = (uint32_t)(a_r0 * 64 + (a_c0 ^ ((a_r0 >> 1) & 3)) * 16);
    uint32_t dA1 = (uint32_t)(a_r1 * 64 + (a_c0 ^ ((a_r1 >> 1) & 3)) * 16);
    // B: 512 chunks -> 2/thread. k = ci>>4, c = ci&15
    int b_k0 = tid >> 4,          b_c0 = tid & 15;
    int b_k1 = (tid + 256) >> 4;
    const __half* Bg0 = g_Wh + (size_t)b_k0 * N + bcol + b_c0 * 8;
    const __half* Bg1 = g_Wh + (size_t)b_k1 * N + bcol + b_c0 * 8;
    uint32_t dB0 = (uint32_t)(b_k0 * 256 + (b_c0 ^ (b_k0 & 7)) * 16);
    uint32_t dB1 = (uint32_t)(b_k1 * 256 + (b_c0 ^ (b_k1 & 7)) * 16);

    int wm = (wid & 1) * 64;     // 2 warp rows
    int wn = (wid >> 1) * 32;    // 4 warp cols

    float acc[4][4][4];
    #pragma unroll
    for (int mf = 0; mf < 4; mf++)
        #pragma unroll
        for (int nf = 0; nf < 4; nf++)
            #pragma unroll
            for (int r = 0; r < 4; r++) acc[mf][nf][r] = 0.0f;

    // ldmatrix smem offsets (buffer-relative)
    uint32_t a_off[4][2];
    #pragma unroll
    for (int mf = 0; mf < 4; mf++)
        #pragma unroll
        for (int ks = 0; ks < 2; ks++) {
            int row = wm + mf * 16 + (lane & 15);
            int c   = ks * 2 + (lane >> 4);
            a_off[mf][ks] = (uint32_t)(row * 64 + (c ^ ((row >> 1) & 3)) * 16);
        }
    uint32_t b_off[2][2];
    #pragma unroll
    for (int nt = 0; nt < 2; nt++)
        #pragma unroll
        for (int ks = 0; ks < 2; ks++) {
            int k = ks * 16 + (lane & 15);
            int c = (wn >> 3) + nt * 2 + (lane >> 4);
            b_off[nt][ks] = (uint32_t)(k * 256 + (c ^ (k & 7)) * 16);
        }

    // prologue
    cp_async16(sA_u + dA0, Ag0);
    cp_async16(sA_u + dA1, Ag1);
    cp_async16(sB_u + dB0, Bg0);
    cp_async16(sB_u + dB1, Bg1);
    CP_COMMIT();

    const int NT = K / GBK;   // 32
    int buf = 0;
    #pragma unroll 1
    for (int t = 0; t < NT; t++) {
        if (t + 1 < NT) {
            int k0g = (t + 1) * GBK;
            uint32_t ab = sA_u + (buf ^ 1) * ASZ;
            uint32_t bb = sB_u + (buf ^ 1) * BSZ;
            cp_async16(ab + dA0, Ag0 + k0g);
            cp_async16(ab + dA1, Ag1 + k0g);
            cp_async16(bb + dB0, Bg0 + (size_t)k0g * N);
            cp_async16(bb + dB1, Bg1 + (size_t)k0g * N);
            CP_COMMIT();
            CP_WAIT(1);
        } else {
            CP_WAIT(0);
        }
        __syncthreads();

        uint32_t Ab = sA_u + buf * ASZ;
        uint32_t Bb = sB_u + buf * BSZ;
        #pragma unroll
        for (int ks = 0; ks < 2; ks++) {
            uint32_t af[4][4], bf[2][4];
            #pragma unroll
            for (int mf = 0; mf < 4; mf++)
                ldsm_x4(af[mf][0], af[mf][1], af[mf][2], af[mf][3],
                        Ab + a_off[mf][ks]);
            #pragma unroll
            for (int nt = 0; nt < 2; nt++)
                ldsm_x4_t(bf[nt][0], bf[nt][1], bf[nt][2], bf[nt][3],
                          Bb + b_off[nt][ks]);
            #pragma unroll
            for (int mf = 0; mf < 4; mf++)
                #pragma unroll
                for (int nt = 0; nt < 2; nt++) {
                    mma_f16(acc[mf][2*nt][0],   acc[mf][2*nt][1],
                            acc[mf][2*nt][2],   acc[mf][2*nt][3],
                            af[mf][0], af[mf][1], af[mf][2], af[mf][3],
                            bf[nt][0], bf[nt][1]);
                    mma_f16(acc[mf][2*nt+1][0], acc[mf][2*nt+1][1],
                            acc[mf][2*nt+1][2], acc[mf][2*nt+1][3],
                            af[mf][0], af[mf][1], af[mf][2], af[mf][3],
                            bf[nt][2], bf[nt][3]);
                }
        }
        __syncthreads();
        buf ^= 1;
    }

    // epilogue: + bias, softplus, store
    #pragma unroll
    for (int nf = 0; nf < 4; nf++) {
        int col = bcol + wn + nf * 8 + tg * 2;
        float bv0 = bias[col], bv1 = bias[col + 1];
        #pragma unroll
        for (int mf = 0; mf < 4; mf++) {
            int row0 = brow + wm + mf * 16 + g;
            float2 o0, o1;
            o0.x = softplus_f(acc[mf][nf][0] + bv0);
            o0.y = softplus_f(acc[mf][nf][1] + bv1);
            o1.x = softplus_f(acc[mf][nf][2] + bv0);
            o1.y = softplus_f(acc[mf][nf][3] + bv1);
            *(float2*)&g_delta[(size_t)row0 * N + col]       = o0;
            *(float2*)&g_delta[(size_t)(row0 + 8) * N + col] = o1;
        }
    }
}

// ---------------- kernel 2: Bm = x@Wb+bb, Cm = x@Wc+bc ----------------
__global__ __launch_bounds__(256) void bc_kernel(
    const float* __restrict__ X,
    const float* __restrict__ Wb, const float* __restrict__ bbv,
    const float* __restrict__ Wc, const float* __restrict__ bcv)
{
    __shared__ __align__(16) float Ws[128][32];
    __shared__ __align__(16) float Xs[8][128];
    int tid  = threadIdx.x;
    int lane = tid & 31;
    int warp = tid >> 5;
    int row0 = blockIdx.x * 8;

    float acc = 0.0f;
    for (int kt = 0; kt < DMODEL; kt += 128) {
        __syncthreads();
        {
            int r  = tid >> 1;
            int hs = tid & 1;
            const float* src = (hs ? Wc : Wb) + (size_t)(kt + r) * NSTATE;
            float4 v0 = ((const float4*)src)[0];
            float4 v1 = ((const float4*)src)[1];
            float4 v2 = ((const float4*)src)[2];
            float4 v3 = ((const float4*)src)[3];
            int cb = hs * 16;
            *(float4*)&Ws[r][cb + 0]  = v0;
            *(float4*)&Ws[r][cb + 4]  = v1;
            *(float4*)&Ws[r][cb + 8]  = v2;
            *(float4*)&Ws[r][cb + 12] = v3;
        }
        {
            int rr = tid >> 5;
            int cc = (tid & 31) * 4;
            *(float4*)&Xs[rr][cc] =
                *(const float4*)(X + (size_t)(row0 + rr) * DMODEL + kt + cc);
        }
        __syncthreads();
        #pragma unroll 8
        for (int kk = 0; kk < 128; kk++)
            acc = fmaf(Xs[warp][kk], Ws[kk][lane], acc);
    }
    acc += (lane < NSTATE) ? bbv[lane] : bcv[lane - NSTATE];
    int row = row0 + warp;
    if (lane < NSTATE) g_Bm[row * NSTATE + lane] = acc;
    else               g_Cm[row * NSTATE + lane - NSTATE] = acc;
}

// ---------------- kernel 3: scan phase A (4 threads per d, 4 states each) --
__global__ __launch_bounds__(256) void scan_phaseA(const float* __restrict__ X)
{
    int tid = threadIdx.x;
    int d   = blockIdx.x * 64 + (tid >> 2);
    int q   = tid & 3;
    int c   = blockIdx.y;
    int b   = blockIdx.z;

    __shared__ __align__(16) float Bsm[CLEN][NSTATE];
    {
        const float4* src = (const float4*)(g_Bm + (size_t)(b * SEQ + c * CLEN) * NSTATE);
        ((float4*)Bsm)[tid] = src[tid];
    }
    float A2r[4];
    *(float4*)&A2r[0] = *(const float4*)(g_A2 + (size_t)d * NSTATE + q * 4);
    __syncthreads();

    float P[4], E[4];
    #pragma unroll
    for (int n = 0; n < 4; n++) { P[n] = 1.0f; E[n] = 0.0f; }

    size_t xoff = (size_t)(b * SEQ + c * CLEN) * DMODEL + d;
    const float* xp = X + xoff;
    const float* dp = g_delta + xoff;

    #pragma unroll 4
    for (int t = 0; t < CLEN; t++) {
        float xv = xp[(size_t)t * DMODEL];
        float dt = dp[(size_t)t * DMODEL];
        float dx = dt * xv;
        float bl[4];
        *(float4*)&bl[0] = *(const float4*)&Bsm[t][q * 4];
        #pragma unroll
        for (int n = 0; n < 4; n++) {
            float a = ex2(dt * A2r[n]);
            P[n] *= a;
            E[n] = fmaf(a, E[n], dx * bl[n]);
        }
    }

    size_t off = ((size_t)((b * NCHUNK + c) * DMODEL + d)) * NSTATE + q * 4;
    *(float4*)(g_P + off) = *(float4*)&P[0];
    *(float4*)(g_E + off) = *(float4*)&E[0];
}

// ---------------- kernel 4: scan phase B ----------------
__global__ __launch_bounds__(256) void scan_phaseB()
{
    int idx = blockIdx.x * 256 + threadIdx.x;
    int b   = idx >> 14;
    int rem = idx & 16383;
    size_t base = (size_t)b * NCHUNK * DMODEL * NSTATE + rem;
    float h = 0.0f;
    #pragma unroll
    for (int c = 0; c < NCHUNK; c++) {
        size_t off = base + (size_t)c * (DMODEL * NSTATE);
        g_hin[off] = h;
        h = fmaf(g_P[off], h, g_E[off]);
    }
}

// ---------------- kernel 5: scan phase C (4 threads per d, shfl combine) ----
__global__ __launch_bounds__(256) void scan_phaseC(
    const float* __restrict__ X, const float* __restrict__ Dskip,
    float* __restrict__ Y)
{
    int tid = threadIdx.x;
    int d   = blockIdx.x * 64 + (tid >> 2);
    int q   = tid & 3;
    int c   = blockIdx.y;
    int b   = blockIdx.z;

    __shared__ __align__(16) float Bsm[CLEN][NSTATE];
    __shared__ __align__(16) float Csm[CLEN][NSTATE];
    {
        size_t so = (size_t)(b * SEQ + c * CLEN) * NSTATE;
        ((float4*)Bsm)[tid] = ((const float4*)(g_Bm + so))[tid];
        ((float4*)Csm)[tid] = ((const float4*)(g_Cm + so))[tid];
    }
    float A2r[4];
    *(float4*)&A2r[0] = *(const float4*)(g_A2 + (size_t)d * NSTATE + q * 4);
    float h[4];
    {
        size_t off = ((size_t)((b * NCHUNK + c) * DMODEL + d)) * NSTATE + q * 4;
        *(float4*)&h[0] = *(const float4*)(g_hin + off);
    }
    float dsk = Dskip[d];
    __syncthreads();

    size_t xoff = (size_t)(b * SEQ + c * CLEN) * DMODEL + d;
    const float* xp = X + xoff;
    const float* dp = g_delta + xoff;
    float* yp = Y + xoff;

    #pragma unroll 4
    for (int t = 0; t < CLEN; t++) {
        float xv = xp[(size_t)t * DMODEL];
        float dt = dp[(size_t)t * DMODEL];
        float dx = dt * xv;
        float bl[4], cl[4];
        *(float4*)&bl[0] = *(const float4*)&Bsm[t][q * 4];
        *(float4*)&cl[0] = *(const float4*)&Csm[t][q * 4];
        float acc0 = 0.0f, acc1 = 0.0f;
        #pragma unroll
        for (int n = 0; n < 4; n += 2) {
            float a0 = ex2(dt * A2r[n]);
            float a1 = ex2(dt * A2r[n + 1]);
            h[n]     = fmaf(a0, h[n],     dx * bl[n]);
            h[n + 1] = fmaf(a1, h[n + 1], dx * bl[n + 1]);
            acc0 = fmaf(h[n],     cl[n],     acc0);
            acc1 = fmaf(h[n + 1], cl[n + 1], acc1);
        }
        float acc = acc0 + acc1;
        acc += __shfl_xor_sync(0xFFFFFFFFu, acc, 1);
        acc += __shfl_xor_sync(0xFFFFFFFFu, acc, 2);
        if (q == 0)
            yp[(size_t)t * DMODEL] = acc + xv * dsk;
    }
}

// ---------------- launch ----------------
extern "C" void kernel_launch(void* const* d_in, const int* in_sizes, int n_in,
                              void* d_out, int out_size)
{
    const float* x     = (const float*)d_in[0];
    const float* A_log = (const float*)d_in[1];
    const float* Dsk   = (const float*)d_in[2];
    const float* Wd    = (const float*)d_in[3];
    const float* bd    = (const float*)d_in[4];
    const float* Wb    = (const float*)d_in[5];
    const float* bb    = (const float*)d_in[6];
    const float* Wc    = (const float*)d_in[7];
    const float* bc    = (const float*)d_in[8];
    float* y = (float*)d_out;

    __half* xh_sym = nullptr;
    __half* wh_sym = nullptr;
    cudaGetSymbolAddress((void**)&xh_sym, g_Xh);
    cudaGetSymbolAddress((void**)&wh_sym, g_Wh);
    cudaFuncSetAttribute(gemm_f16_softplus,
                         cudaFuncAttributeMaxDynamicSharedMemorySize,
                         GEMM_SMEM);

    prep_A2_kernel<<<(DMODEL*NSTATE + 255) / 256, 256>>>(A_log);
    convert_f16_kernel<<<(MROWS * DMODEL / 4) / 256, 256>>>(x, xh_sym);
    convert_f16_kernel<<<(DMODEL * DMODEL / 4) / 256, 256>>>(Wd, wh_sym);
    gemm_f16_softplus<<<dim3(DMODEL / GBN, MROWS / GBM), 256, GEMM_SMEM>>>(bd);
    bc_kernel<<<MROWS / 8, 256>>>(x, Wb, bb, Wc, bc);
    scan_phaseA<<<dim3(DMODEL / 64, NCHUNK, B_SZ), 256>>>(x);
    scan_phaseB<<<(B_SZ * DMODEL * NSTATE) / 256, 256>>>();
    scan_phaseC<<<dim3(DMODEL / 64, NCHUNK, B_SZ), 256>>>(x, Dsk, y);
}

// round 9
// speedup vs baseline: 1.1126x; 1.1126x over previous
#include <cuda_runtime.h>
#include <cuda_fp16.h>
#include <cuda_bf16.h>
#include <math.h>
#include <stdint.h>

// Problem constants
#define B_SZ   4
#define SEQ    2048
#define DMODEL 1024
#define NSTATE 16
#define MROWS  (B_SZ*SEQ)        // 8192
#define NCHUNK 32
#define CLEN   64                // NCHUNK*CLEN == SEQ

// ---------------- device scratch (no allocations allowed) ----------------
__device__ __align__(16) float g_delta[MROWS*DMODEL];
__device__ __align__(16) float g_Bm[MROWS*NSTATE];
__device__ __align__(16) float g_Cm[MROWS*NSTATE];
__device__ __align__(16) float g_A2[DMODEL*NSTATE];
__device__ __align__(16) float g_P [B_SZ*NCHUNK*DMODEL*NSTATE];
__device__ __align__(16) float g_E [B_SZ*NCHUNK*DMODEL*NSTATE];
__device__ __align__(16) float g_hin[B_SZ*NCHUNK*DMODEL*NSTATE];
__device__ __align__(16) __half g_Xh[MROWS*DMODEL];    // fp16 X      16 MB
__device__ __align__(16) __half g_Wh[DMODEL*DMODEL];   // fp16 Wd     2 MB

// ---------------- helpers ----------------
__device__ __forceinline__ float ex2(float x) {
    float r;
    asm("ex2.approx.ftz.f32 %0, %1;" : "=f"(r) : "f"(x));
    return r;
}
__device__ __forceinline__ float softplus_f(float z) {
    return fmaxf(z, 0.0f) + log1pf(__expf(-fabsf(z)));
}
__device__ __forceinline__ uint32_t smem_u32(const void* p) {
    uint32_t a;
    asm("{ .reg .u64 t; cvta.to.shared.u64 t, %1; cvt.u32.u64 %0, t; }"
        : "=r"(a) : "l"(p));
    return a;
}
__device__ __forceinline__ void cp_async16(uint32_t dst, const void* src) {
    asm volatile("cp.async.cg.shared.global [%0], [%1], 16;" :: "r"(dst), "l"(src));
}
#define CP_COMMIT() asm volatile("cp.async.commit_group;" ::: "memory")
#define CP_WAIT(n)  asm volatile("cp.async.wait_group %0;" :: "n"(n) : "memory")

__device__ __forceinline__ void ldsm_x4(
    uint32_t& r0, uint32_t& r1, uint32_t& r2, uint32_t& r3, uint32_t addr)
{
    asm volatile("ldmatrix.sync.aligned.m8n8.x4.shared.b16 {%0,%1,%2,%3}, [%4];"
                 : "=r"(r0), "=r"(r1), "=r"(r2), "=r"(r3) : "r"(addr));
}
__device__ __forceinline__ void ldsm_x4_t(
    uint32_t& r0, uint32_t& r1, uint32_t& r2, uint32_t& r3, uint32_t addr)
{
    asm volatile("ldmatrix.sync.aligned.m8n8.x4.trans.shared.b16 {%0,%1,%2,%3}, [%4];"
                 : "=r"(r0), "=r"(r1), "=r"(r2), "=r"(r3) : "r"(addr));
}
__device__ __forceinline__ void mma_f16(
    float& d0, float& d1, float& d2, float& d3,
    uint32_t a0, uint32_t a1, uint32_t a2, uint32_t a3,
    uint32_t b0, uint32_t b1)
{
    asm volatile(
        "mma.sync.aligned.m16n8k16.row.col.f32.f16.f16.f32 "
        "{%0,%1,%2,%3}, {%4,%5,%6,%7}, {%8,%9}, {%0,%1,%2,%3};"
        : "+f"(d0), "+f"(d1), "+f"(d2), "+f"(d3)
        : "r"(a0), "r"(a1), "r"(a2), "r"(a3), "r"(b0), "r"(b1));
}

// ---------------- kernel 0: A2 = -exp(A_log) * log2(e) ----------------
__global__ void prep_A2_kernel(const float* __restrict__ A_log) {
    int i = blockIdx.x * 256 + threadIdx.x;
    if (i < DMODEL*NSTATE)
        g_A2[i] = -__expf(A_log[i]) * 1.44269504088896f;
}

// ---------------- conversion: fp32 -> fp16 ----------------
__global__ __launch_bounds__(256) void convert_f16_kernel(
    const float* __restrict__ src, __half* __restrict__ dst)
{
    int i4 = blockIdx.x * 256 + threadIdx.x;
    float4 v = ((const float4*)src)[i4];
    __half2 h0 = __floats2half2_rn(v.x, v.y);
    __half2 h1 = __floats2half2_rn(v.z, v.w);
    ((__half2*)dst)[i4*2]   = h0;
    ((__half2*)dst)[i4*2+1] = h1;
}

// ---------------- kernel 1: delta = softplus(x @ Wd + bd), fp16 mma ------
// 128x128 block, 256 threads, 2 CTAs/SM, warp tile 64x32, cp.async dbuf.
// K tile = 64 (two 32-k sub-tiles, each with R6-proven swizzle):
//   A sub: [128 m][32 k] half, 64B/row, swz c^=((row>>1)&3), 8KB
//   B sub: [32 k][128 n] half, 256B/row, swz c^=(k&7), 8KB
#define GBM 128
#define GBN 128
#define GBK 64
#define SUBSZ 8192
#define ASZ 16384     // bytes per A buffer (2 subs)
#define BSZ 16384     // bytes per B buffer (2 subs)
#define GEMM_SMEM (2*(ASZ+BSZ))   // 65536

__global__ __launch_bounds__(256, 2) void gemm_f16_softplus(
    const float* __restrict__ bias)
{
    const int K = DMODEL, N = DMODEL;
    extern __shared__ __align__(128) char smem[];
    uint32_t sA_u = smem_u32(smem);              // 2 x 16KB
    uint32_t sB_u = sA_u + 2*ASZ;                // 2 x 16KB

    int tid  = threadIdx.x;
    int wid  = tid >> 5, lane = tid & 31;
    int g    = lane >> 2, tg = lane & 3;
    int brow = blockIdx.y * GBM;
    int bcol = blockIdx.x * GBN;

    // cp.async mappings (16B chunks), 4 chunks per thread per operand.
    // A: ci = tid + j*256 (0..1023): row = ci>>3 (c8 = tid&7 const), sub = c8>>2
    int a_c8  = tid & 7;
    int a_sub = a_c8 >> 2, a_c = a_c8 & 3;
    int a_row0 = tid >> 3;                       // + j*32
    // B: ci = tid + j*256: k = ci>>4 (c = tid&15 const)
    int b_c  = tid & 15;
    int b_k0 = tid >> 4;                         // + j*16

    const __half* Ag[4];
    const __half* Bg[4];
    uint32_t dA[4], dB[4];
    #pragma unroll
    for (int j = 0; j < 4; j++) {
        int ar = a_row0 + j * 32;
        Ag[j] = g_Xh + (size_t)(brow + ar) * K + a_c8 * 8;
        dA[j] = (uint32_t)(a_sub * SUBSZ + ar * 64 + (a_c ^ ((ar >> 1) & 3)) * 16);
        int bk = b_k0 + j * 16;                  // 0..63
        int bsub = bk >> 5, bkin = bk & 31;
        Bg[j] = g_Wh + (size_t)bk * N + bcol + b_c * 8;
        dB[j] = (uint32_t)(bsub * SUBSZ + bkin * 256 + (b_c ^ (bkin & 7)) * 16);
    }

    int wm = (wid & 1) * 64;     // 2 warp rows
    int wn = (wid >> 1) * 32;    // 4 warp cols

    float acc[4][4][4];
    #pragma unroll
    for (int mf = 0; mf < 4; mf++)
        #pragma unroll
        for (int nf = 0; nf < 4; nf++)
            #pragma unroll
            for (int r = 0; r < 4; r++) acc[mf][nf][r] = 0.0f;

    // ldmatrix smem offsets (sub-tile relative; add sub*SUBSZ at use)
    uint32_t a_off[4][2];
    #pragma unroll
    for (int mf = 0; mf < 4; mf++)
        #pragma unroll
        for (int ks = 0; ks < 2; ks++) {
            int row = wm + mf * 16 + (lane & 15);
            int c   = ks * 2 + (lane >> 4);
            a_off[mf][ks] = (uint32_t)(row * 64 + (c ^ ((row >> 1) & 3)) * 16);
        }
    uint32_t b_off[2][2];
    #pragma unroll
    for (int nt = 0; nt < 2; nt++)
        #pragma unroll
        for (int ks = 0; ks < 2; ks++) {
            int k = ks * 16 + (lane & 15);
            int c = (wn >> 3) + nt * 2 + (lane >> 4);
            b_off[nt][ks] = (uint32_t)(k * 256 + (c ^ (k & 7)) * 16);
        }

    // prologue: tile 0 -> buffer 0
    #pragma unroll
    for (int j = 0; j < 4; j++) {
        cp_async16(sA_u + dA[j], Ag[j]);
        cp_async16(sB_u + dB[j], Bg[j]);
    }
    CP_COMMIT();

    const int NT = K / GBK;   // 16
    int buf = 0;
    #pragma unroll 1
    for (int t = 0; t < NT; t++) {
        if (t + 1 < NT) {
            int k0g = (t + 1) * GBK;
            uint32_t ab = sA_u + (buf ^ 1) * ASZ;
            uint32_t bb = sB_u + (buf ^ 1) * BSZ;
            #pragma unroll
            for (int j = 0; j < 4; j++) {
                cp_async16(ab + dA[j], Ag[j] + k0g);
                cp_async16(bb + dB[j], Bg[j] + (size_t)k0g * N);
            }
            CP_COMMIT();
            CP_WAIT(1);
        } else {
            CP_WAIT(0);
        }
        __syncthreads();

        uint32_t Ab = sA_u + buf * ASZ;
        uint32_t Bb = sB_u + buf * BSZ;
        #pragma unroll
        for (int ks = 0; ks < 4; ks++) {
            uint32_t As = Ab + (ks >> 1) * SUBSZ;
            uint32_t Bs = Bb + (ks >> 1) * SUBSZ;
            int ksl = ks & 1;
            uint32_t af[4][4], bf[2][4];
            #pragma unroll
            for (int mf = 0; mf < 4; mf++)
                ldsm_x4(af[mf][0], af[mf][1], af[mf][2], af[mf][3],
                        As + a_off[mf][ksl]);
            #pragma unroll
            for (int nt = 0; nt < 2; nt++)
                ldsm_x4_t(bf[nt][0], bf[nt][1], bf[nt][2], bf[nt][3],
                          Bs + b_off[nt][ksl]);
            #pragma unroll
            for (int mf = 0; mf < 4; mf++)
                #pragma unroll
                for (int nt = 0; nt < 2; nt++) {
                    mma_f16(acc[mf][2*nt][0],   acc[mf][2*nt][1],
                            acc[mf][2*nt][2],   acc[mf][2*nt][3],
                            af[mf][0], af[mf][1], af[mf][2], af[mf][3],
                            bf[nt][0], bf[nt][1]);
                    mma_f16(acc[mf][2*nt+1][0], acc[mf][2*nt+1][1],
                            acc[mf][2*nt+1][2], acc[mf][2*nt+1][3],
                            af[mf][0], af[mf][1], af[mf][2], af[mf][3],
                            bf[nt][2], bf[nt][3]);
                }
        }
        __syncthreads();
        buf ^= 1;
    }

    // epilogue: + bias, softplus, store
    #pragma unroll
    for (int nf = 0; nf < 4; nf++) {
        int col = bcol + wn + nf * 8 + tg * 2;
        float bv0 = bias[col], bv1 = bias[col + 1];
        #pragma unroll
        for (int mf = 0; mf < 4; mf++) {
            int row0 = brow + wm + mf * 16 + g;
            float2 o0, o1;
            o0.x = softplus_f(acc[mf][nf][0] + bv0);
            o0.y = softplus_f(acc[mf][nf][1] + bv1);
            o1.x = softplus_f(acc[mf][nf][2] + bv0);
            o1.y = softplus_f(acc[mf][nf][3] + bv1);
            *(float2*)&g_delta[(size_t)row0 * N + col]       = o0;
            *(float2*)&g_delta[(size_t)(row0 + 8) * N + col] = o1;
        }
    }
}

// ---------------- kernel 2: Bm = x@Wb+bb, Cm = x@Wc+bc ----------------
__global__ __launch_bounds__(256) void bc_kernel(
    const float* __restrict__ X,
    const float* __restrict__ Wb, const float* __restrict__ bbv,
    const float* __restrict__ Wc, const float* __restrict__ bcv)
{
    __shared__ __align__(16) float Ws[128][32];
    __shared__ __align__(16) float Xs[8][128];
    int tid  = threadIdx.x;
    int lane = tid & 31;
    int warp = tid >> 5;
    int row0 = blockIdx.x * 8;

    float acc = 0.0f;
    for (int kt = 0; kt < DMODEL; kt += 128) {
        __syncthreads();
        {
            int r  = tid >> 1;
            int hs = tid & 1;
            const float* src = (hs ? Wc : Wb) + (size_t)(kt + r) * NSTATE;
            float4 v0 = ((const float4*)src)[0];
            float4 v1 = ((const float4*)src)[1];
            float4 v2 = ((const float4*)src)[2];
            float4 v3 = ((const float4*)src)[3];
            int cb = hs * 16;
            *(float4*)&Ws[r][cb + 0]  = v0;
            *(float4*)&Ws[r][cb + 4]  = v1;
            *(float4*)&Ws[r][cb + 8]  = v2;
            *(float4*)&Ws[r][cb + 12] = v3;
        }
        {
            int rr = tid >> 5;
            int cc = (tid & 31) * 4;
            *(float4*)&Xs[rr][cc] =
                *(const float4*)(X + (size_t)(row0 + rr) * DMODEL + kt + cc);
        }
        __syncthreads();
        #pragma unroll 8
        for (int kk = 0; kk < 128; kk++)
            acc = fmaf(Xs[warp][kk], Ws[kk][lane], acc);
    }
    acc += (lane < NSTATE) ? bbv[lane] : bcv[lane - NSTATE];
    int row = row0 + warp;
    if (lane < NSTATE) g_Bm[row * NSTATE + lane] = acc;
    else               g_Cm[row * NSTATE + lane - NSTATE] = acc;
}

// ---------------- kernel 3: scan phase A (2 threads per d, 8 states each) --
__global__ __launch_bounds__(256) void scan_phaseA(const float* __restrict__ X)
{
    int tid  = threadIdx.x;
    int d    = blockIdx.x * 128 + (tid >> 1);
    int half = tid & 1;
    int c    = blockIdx.y;
    int b    = blockIdx.z;

    __shared__ __align__(16) float Bsm[CLEN][NSTATE];
    {
        const float4* src = (const float4*)(g_Bm + (size_t)(b * SEQ + c * CLEN) * NSTATE);
        ((float4*)Bsm)[tid] = src[tid];
    }
    float A2r[8];
    {
        const float4* ap = (const float4*)(g_A2 + (size_t)d * NSTATE + half * 8);
        *(float4*)&A2r[0] = ap[0];
        *(float4*)&A2r[4] = ap[1];
    }
    __syncthreads();

    float P[8], E[8];
    #pragma unroll
    for (int n = 0; n < 8; n++) { P[n] = 1.0f; E[n] = 0.0f; }

    size_t xoff = (size_t)(b * SEQ + c * CLEN) * DMODEL + d;
    const float* xp = X + xoff;
    const float* dp = g_delta + xoff;

    #pragma unroll 4
    for (int t = 0; t < CLEN; t++) {
        float xv = xp[(size_t)t * DMODEL];
        float dt = dp[(size_t)t * DMODEL];
        float dx = dt * xv;
        float bl[8];
        const float4* bp = (const float4*)&Bsm[t][half * 8];
        *(float4*)&bl[0] = bp[0];
        *(float4*)&bl[4] = bp[1];
        #pragma unroll
        for (int n = 0; n < 8; n++) {
            float a = ex2(dt * A2r[n]);
            P[n] *= a;
            E[n] = fmaf(a, E[n], dx * bl[n]);
        }
    }

    size_t off = ((size_t)((b * NCHUNK + c) * DMODEL + d)) * NSTATE + half * 8;
    float4* Pp = (float4*)(g_P + off);
    float4* Ep = (float4*)(g_E + off);
    Pp[0] = *(float4*)&P[0];  Pp[1] = *(float4*)&P[4];
    Ep[0] = *(float4*)&E[0];  Ep[1] = *(float4*)&E[4];
}

// ---------------- kernel 4: scan phase B ----------------
__global__ __launch_bounds__(256) void scan_phaseB()
{
    int idx = blockIdx.x * 256 + threadIdx.x;
    int b   = idx >> 14;
    int rem = idx & 16383;
    size_t base = (size_t)b * NCHUNK * DMODEL * NSTATE + rem;
    float h = 0.0f;
    #pragma unroll
    for (int c = 0; c < NCHUNK; c++) {
        size_t off = base + (size_t)c * (DMODEL * NSTATE);
        g_hin[off] = h;
        h = fmaf(g_P[off], h, g_E[off]);
    }
}

// ---------------- kernel 5: scan phase C (2 threads per d, shfl combine) ----
__global__ __launch_bounds__(256) void scan_phaseC(
    const float* __restrict__ X, const float* __restrict__ Dskip,
    float* __restrict__ Y)
{
    int tid  = threadIdx.x;
    int d    = blockIdx.x * 128 + (tid >> 1);
    int half = tid & 1;
    int c    = blockIdx.y;
    int b    = blockIdx.z;

    __shared__ __align__(16) float Bsm[CLEN][NSTATE];
    __shared__ __align__(16) float Csm[CLEN][NSTATE];
    {
        size_t so = (size_t)(b * SEQ + c * CLEN) * NSTATE;
        ((float4*)Bsm)[tid] = ((const float4*)(g_Bm + so))[tid];
        ((float4*)Csm)[tid] = ((const float4*)(g_Cm + so))[tid];
    }
    float A2r[8];
    {
        const float4* ap = (const float4*)(g_A2 + (size_t)d * NSTATE + half * 8);
        *(float4*)&A2r[0] = ap[0];
        *(float4*)&A2r[4] = ap[1];
    }
    float h[8];
    {
        size_t off = ((size_t)((b * NCHUNK + c) * DMODEL + d)) * NSTATE + half * 8;
        const float4* hp = (const float4*)(g_hin + off);
        *(float4*)&h[0] = hp[0];
        *(float4*)&h[4] = hp[1];
    }
    float dsk = Dskip[d];
    __syncthreads();

    size_t xoff = (size_t)(b * SEQ + c * CLEN) * DMODEL + d;
    const float* xp = X + xoff;
    const float* dp = g_delta + xoff;
    float* yp = Y + xoff;

    #pragma unroll 4
    for (int t = 0; t < CLEN; t++) {
        float xv = xp[(size_t)t * DMODEL];
        float dt = dp[(size_t)t * DMODEL];
        float dx = dt * xv;
        float bl[8], cl[8];
        const float4* bp = (const float4*)&Bsm[t][half * 8];
        const float4* cp = (const float4*)&Csm[t][half * 8];
        *(float4*)&bl[0] = bp[0]; *(float4*)&bl[4] = bp[1];
        *(float4*)&cl[0] = cp[0]; *(float4*)&cl[4] = cp[1];
        float acc0 = 0.0f, acc1 = 0.0f;
        #pragma unroll
        for (int n = 0; n < 8; n += 2) {
            float a0 = ex2(dt * A2r[n]);
            float a1 = ex2(dt * A2r[n + 1]);
            h[n]     = fmaf(a0, h[n],     dx * bl[n]);
            h[n + 1] = fmaf(a1, h[n + 1], dx * bl[n + 1]);
            acc0 = fmaf(h[n],     cl[n],     acc0);
            acc1 = fmaf(h[n + 1], cl[n + 1], acc1);
        }
        float acc = acc0 + acc1;
        acc += __shfl_xor_sync(0xFFFFFFFFu, acc, 1);
        if (half == 0)
            yp[(size_t)t * DMODEL] = acc + xv * dsk;
    }
}

// ---------------- launch ----------------
extern "C" void kernel_launch(void* const* d_in, const int* in_sizes, int n_in,
                              void* d_out, int out_size)
{
    const float* x     = (const float*)d_in[0];
    const float* A_log = (const float*)d_in[1];
    const float* Dsk   = (const float*)d_in[2];
    const float* Wd    = (const float*)d_in[3];
    const float* bd    = (const float*)d_in[4];
    const float* Wb    = (const float*)d_in[5];
    const float* bb    = (const float*)d_in[6];
    const float* Wc    = (const float*)d_in[7];
    const float* bc    = (const float*)d_in[8];
    float* y = (float*)d_out;

    __half* xh_sym = nullptr;
    __half* wh_sym = nullptr;
    cudaGetSymbolAddress((void**)&xh_sym, g_Xh);
    cudaGetSymbolAddress((void**)&wh_sym, g_Wh);
    cudaFuncSetAttribute(gemm_f16_softplus,
                         cudaFuncAttributeMaxDynamicSharedMemorySize,
                         GEMM_SMEM);

    prep_A2_kernel<<<(DMODEL*NSTATE + 255) / 256, 256>>>(A_log);
    convert_f16_kernel<<<(MROWS * DMODEL / 4) / 256, 256>>>(x, xh_sym);
    convert_f16_kernel<<<(DMODEL * DMODEL / 4) / 256, 256>>>(Wd, wh_sym);
    gemm_f16_softplus<<<dim3(DMODEL / GBN, MROWS / GBM), 256, GEMM_SMEM>>>(bd);
    bc_kernel<<<MROWS / 8, 256>>>(x, Wb, bb, Wc, bc);
    scan_phaseA<<<dim3(DMODEL / 128, NCHUNK, B_SZ), 256>>>(x);
    scan_phaseB<<<(B_SZ * DMODEL * NSTATE) / 256, 256>>>();
    scan_phaseC<<<dim3(DMODEL / 128, NCHUNK, B_SZ), 256>>>(x, Dsk, y);
}

// round 10
// speedup vs baseline: 1.3847x; 1.2446x over previous
#include <cuda_runtime.h>
#include <cuda_fp16.h>
#include <cuda_bf16.h>
#include <math.h>
#include <stdint.h>

// Problem constants
#define B_SZ   4
#define SEQ    2048
#define DMODEL 1024
#define NSTATE 16
#define MROWS  (B_SZ*SEQ)        // 8192
#define NCHUNK 32
#define CLEN   64                // NCHUNK*CLEN == SEQ

// ---------------- device scratch (no allocations allowed) ----------------
__device__ __align__(16) float g_delta[MROWS*DMODEL];
__device__ __align__(16) float g_Bm[MROWS*NSTATE];
__device__ __align__(16) float g_Cm[MROWS*NSTATE];
__device__ __align__(16) float g_A2[DMODEL*NSTATE];
__device__ __align__(16) float g_P [B_SZ*NCHUNK*DMODEL*NSTATE];
__device__ __align__(16) float g_E [B_SZ*NCHUNK*DMODEL*NSTATE];
__device__ __align__(16) float g_hin[B_SZ*NCHUNK*DMODEL*NSTATE];
__device__ __align__(16) __half g_Xh[MROWS*DMODEL];    // fp16 X      16 MB
__device__ __align__(16) __half g_Wh[DMODEL*DMODEL];   // fp16 Wd     2 MB
__device__ __align__(16) __half g_Wbc[DMODEL*32];      // fp16 [Wb|Wc] 64 KB

// ---------------- helpers ----------------
__device__ __forceinline__ float ex2(float x) {
    float r;
    asm("ex2.approx.ftz.f32 %0, %1;" : "=f"(r) : "f"(x));
    return r;
}
__device__ __forceinline__ float softplus_f(float z) {
    return fmaxf(z, 0.0f) + log1pf(__expf(-fabsf(z)));
}
__device__ __forceinline__ uint32_t smem_u32(const void* p) {
    uint32_t a;
    asm("{ .reg .u64 t; cvta.to.shared.u64 t, %1; cvt.u32.u64 %0, t; }"
        : "=r"(a) : "l"(p));
    return a;
}
__device__ __forceinline__ void cp_async16(uint32_t dst, const void* src) {
    asm volatile("cp.async.cg.shared.global [%0], [%1], 16;" :: "r"(dst), "l"(src));
}
#define CP_COMMIT() asm volatile("cp.async.commit_group;" ::: "memory")
#define CP_WAIT(n)  asm volatile("cp.async.wait_group %0;" :: "n"(n) : "memory")

__device__ __forceinline__ void ldsm_x4(
    uint32_t& r0, uint32_t& r1, uint32_t& r2, uint32_t& r3, uint32_t addr)
{
    asm volatile("ldmatrix.sync.aligned.m8n8.x4.shared.b16 {%0,%1,%2,%3}, [%4];"
                 : "=r"(r0), "=r"(r1), "=r"(r2), "=r"(r3) : "r"(addr));
}
__device__ __forceinline__ void ldsm_x4_t(
    uint32_t& r0, uint32_t& r1, uint32_t& r2, uint32_t& r3, uint32_t addr)
{
    asm volatile("ldmatrix.sync.aligned.m8n8.x4.trans.shared.b16 {%0,%1,%2,%3}, [%4];"
                 : "=r"(r0), "=r"(r1), "=r"(r2), "=r"(r3) : "r"(addr));
}
__device__ __forceinline__ void mma_f16(
    float& d0, float& d1, float& d2, float& d3,
    uint32_t a0, uint32_t a1, uint32_t a2, uint32_t a3,
    uint32_t b0, uint32_t b1)
{
    asm volatile(
        "mma.sync.aligned.m16n8k16.row.col.f32.f16.f16.f32 "
        "{%0,%1,%2,%3}, {%4,%5,%6,%7}, {%8,%9}, {%0,%1,%2,%3};"
        : "+f"(d0), "+f"(d1), "+f"(d2), "+f"(d3)
        : "r"(a0), "r"(a1), "r"(a2), "r"(a3), "r"(b0), "r"(b1));
}

// ---------------- kernel 0: A2 = -exp(A_log) * log2(e) ----------------
__global__ void prep_A2_kernel(const float* __restrict__ A_log) {
    int i = blockIdx.x * 256 + threadIdx.x;
    if (i < DMODEL*NSTATE)
        g_A2[i] = -__expf(A_log[i]) * 1.44269504088896f;
}

// ---------------- conversion: fp32 -> fp16 ----------------
__global__ __launch_bounds__(256) void convert_f16_kernel(
    const float* __restrict__ src, __half* __restrict__ dst)
{
    int i4 = blockIdx.x * 256 + threadIdx.x;
    float4 v = ((const float4*)src)[i4];
    __half2 h0 = __floats2half2_rn(v.x, v.y);
    __half2 h1 = __floats2half2_rn(v.z, v.w);
    ((__half2*)dst)[i4*2]   = h0;
    ((__half2*)dst)[i4*2+1] = h1;
}

// ---------------- pack [Wb | Wc] -> fp16 [1024][32] ----------------
__global__ __launch_bounds__(256) void pack_wbc_kernel(
    const float* __restrict__ Wb, const float* __restrict__ Wc)
{
    int i = blockIdx.x * 256 + threadIdx.x;   // 0 .. 32767
    int k = i >> 5, n = i & 31;
    float v = (n < 16) ? Wb[k * 16 + n] : Wc[k * 16 + n - 16];
    g_Wbc[i] = __float2half_rn(v);
}

// ---------------- kernel 1: delta = softplus(x @ Wd + bd), fp16 mma ------
// 128x128 block, 256 threads, 2 CTAs/SM, warp tile 64x32, cp.async dbuf.
#define GBM 128
#define GBN 128
#define GBK 64
#define SUBSZ 8192
#define ASZ 16384
#define BSZ 16384
#define GEMM_SMEM (2*(ASZ+BSZ))   // 65536

__global__ __launch_bounds__(256, 2) void gemm_f16_softplus(
    const float* __restrict__ bias)
{
    const int K = DMODEL, N = DMODEL;
    extern __shared__ __align__(128) char smem[];
    uint32_t sA_u = smem_u32(smem);
    uint32_t sB_u = sA_u + 2*ASZ;

    int tid  = threadIdx.x;
    int wid  = tid >> 5, lane = tid & 31;
    int g    = lane >> 2, tg = lane & 3;
    int brow = blockIdx.y * GBM;
    int bcol = blockIdx.x * GBN;

    int a_c8  = tid & 7;
    int a_sub = a_c8 >> 2, a_c = a_c8 & 3;
    int a_row0 = tid >> 3;
    int b_c  = tid & 15;
    int b_k0 = tid >> 4;

    const __half* Ag[4];
    const __half* Bg[4];
    uint32_t dA[4], dB[4];
    #pragma unroll
    for (int j = 0; j < 4; j++) {
        int ar = a_row0 + j * 32;
        Ag[j] = g_Xh + (size_t)(brow + ar) * K + a_c8 * 8;
        dA[j] = (uint32_t)(a_sub * SUBSZ + ar * 64 + (a_c ^ ((ar >> 1) & 3)) * 16);
        int bk = b_k0 + j * 16;
        int bsub = bk >> 5, bkin = bk & 31;
        Bg[j] = g_Wh + (size_t)bk * N + bcol + b_c * 8;
        dB[j] = (uint32_t)(bsub * SUBSZ + bkin * 256 + (b_c ^ (bkin & 7)) * 16);
    }

    int wm = (wid & 1) * 64;
    int wn = (wid >> 1) * 32;

    float acc[4][4][4];
    #pragma unroll
    for (int mf = 0; mf < 4; mf++)
        #pragma unroll
        for (int nf = 0; nf < 4; nf++)
            #pragma unroll
            for (int r = 0; r < 4; r++) acc[mf][nf][r] = 0.0f;

    uint32_t a_off[4][2];
    #pragma unroll
    for (int mf = 0; mf < 4; mf++)
        #pragma unroll
        for (int ks = 0; ks < 2; ks++) {
            int row = wm + mf * 16 + (lane & 15);
            int c   = ks * 2 + (lane >> 4);
            a_off[mf][ks] = (uint32_t)(row * 64 + (c ^ ((row >> 1) & 3)) * 16);
        }
    uint32_t b_off[2][2];
    #pragma unroll
    for (int nt = 0; nt < 2; nt++)
        #pragma unroll
        for (int ks = 0; ks < 2; ks++) {
            int k = ks * 16 + (lane & 15);
            int c = (wn >> 3) + nt * 2 + (lane >> 4);
            b_off[nt][ks] = (uint32_t)(k * 256 + (c ^ (k & 7)) * 16);
        }

    #pragma unroll
    for (int j = 0; j < 4; j++) {
        cp_async16(sA_u + dA[j], Ag[j]);
        cp_async16(sB_u + dB[j], Bg[j]);
    }
    CP_COMMIT();

    const int NT = K / GBK;   // 16
    int buf = 0;
    #pragma unroll 1
    for (int t = 0; t < NT; t++) {
        if (t + 1 < NT) {
            int k0g = (t + 1) * GBK;
            uint32_t ab = sA_u + (buf ^ 1) * ASZ;
            uint32_t bb = sB_u + (buf ^ 1) * BSZ;
            #pragma unroll
            for (int j = 0; j < 4; j++) {
                cp_async16(ab + dA[j], Ag[j] + k0g);
                cp_async16(bb + dB[j], Bg[j] + (size_t)k0g * N);
            }
            CP_COMMIT();
            CP_WAIT(1);
        } else {
            CP_WAIT(0);
        }
        __syncthreads();

        uint32_t Ab = sA_u + buf * ASZ;
        uint32_t Bb = sB_u + buf * BSZ;
        #pragma unroll
        for (int ks = 0; ks < 4; ks++) {
            uint32_t As = Ab + (ks >> 1) * SUBSZ;
            uint32_t Bs = Bb + (ks >> 1) * SUBSZ;
            int ksl = ks & 1;
            uint32_t af[4][4], bf[2][4];
            #pragma unroll
            for (int mf = 0; mf < 4; mf++)
                ldsm_x4(af[mf][0], af[mf][1], af[mf][2], af[mf][3],
                        As + a_off[mf][ksl]);
            #pragma unroll
            for (int nt = 0; nt < 2; nt++)
                ldsm_x4_t(bf[nt][0], bf[nt][1], bf[nt][2], bf[nt][3],
                          Bs + b_off[nt][ksl]);
            #pragma unroll
            for (int mf = 0; mf < 4; mf++)
                #pragma unroll
                for (int nt = 0; nt < 2; nt++) {
                    mma_f16(acc[mf][2*nt][0],   acc[mf][2*nt][1],
                            acc[mf][2*nt][2],   acc[mf][2*nt][3],
                            af[mf][0], af[mf][1], af[mf][2], af[mf][3],
                            bf[nt][0], bf[nt][1]);
                    mma_f16(acc[mf][2*nt+1][0], acc[mf][2*nt+1][1],
                            acc[mf][2*nt+1][2], acc[mf][2*nt+1][3],
                            af[mf][0], af[mf][1], af[mf][2], af[mf][3],
                            bf[nt][2], bf[nt][3]);
                }
        }
        __syncthreads();
        buf ^= 1;
    }

    #pragma unroll
    for (int nf = 0; nf < 4; nf++) {
        int col = bcol + wn + nf * 8 + tg * 2;
        float bv0 = bias[col], bv1 = bias[col + 1];
        #pragma unroll
        for (int mf = 0; mf < 4; mf++) {
            int row0 = brow + wm + mf * 16 + g;
            float2 o0, o1;
            o0.x = softplus_f(acc[mf][nf][0] + bv0);
            o0.y = softplus_f(acc[mf][nf][1] + bv1);
            o1.x = softplus_f(acc[mf][nf][2] + bv0);
            o1.y = softplus_f(acc[mf][nf][3] + bv1);
            *(float2*)&g_delta[(size_t)row0 * N + col]       = o0;
            *(float2*)&g_delta[(size_t)(row0 + 8) * N + col] = o1;
        }
    }
}

// ---------------- kernel 2: bc_gemm: [Bm|Cm] = Xh @ Wbc + bias, fp16 mma --
// Block: 64 rows x 32 cols, 128 threads (4 warps), warp tile 16x32.
// A smem: [64 m][32 k] half, 64B/row, swz c^=((row>>1)&3)
// B smem: [32 k][32 n] half, 64B/row, swz c^=((k>>1)&3)
#define BCM 64
#define BC_ASZ 4096
#define BC_BSZ 2048

__global__ __launch_bounds__(128) void bc_gemm(
    const float* __restrict__ bbv, const float* __restrict__ bcv)
{
    __shared__ __align__(128) __half sA[2][BC_ASZ/2];
    __shared__ __align__(128) __half sB[2][BC_BSZ/2];
    uint32_t sA_u = smem_u32(sA);
    uint32_t sB_u = smem_u32(sB);

    int tid  = threadIdx.x;
    int wid  = tid >> 5, lane = tid & 31;
    int g    = lane >> 2, tg = lane & 3;
    int brow = blockIdx.x * BCM;

    // cp.async A: 256 chunks -> 2/thread. row = ci>>2, c = ci&3
    int ar0 = tid >> 2, ac = tid & 3;
    int ar1 = (tid + 128) >> 2;
    const __half* Ag0 = g_Xh + (size_t)(brow + ar0) * DMODEL + ac * 8;
    const __half* Ag1 = g_Xh + (size_t)(brow + ar1) * DMODEL + ac * 8;
    uint32_t dA0 = (uint32_t)(ar0 * 64 + (ac ^ ((ar0 >> 1) & 3)) * 16);
    uint32_t dA1 = (uint32_t)(ar1 * 64 + (ac ^ ((ar1 >> 1) & 3)) * 16);
    // cp.async B: 128 chunks -> 1/thread. k = tid>>2, c = tid&3
    int bk = tid >> 2, bcc = tid & 3;
    const __half* Bg = g_Wbc + (size_t)bk * 32 + bcc * 8;
    uint32_t dB = (uint32_t)(bk * 64 + (bcc ^ ((bk >> 1) & 3)) * 16);

    float acc[4][4];
    #pragma unroll
    for (int nf = 0; nf < 4; nf++)
        #pragma unroll
        for (int r = 0; r < 4; r++) acc[nf][r] = 0.0f;

    // ldmatrix offsets
    uint32_t a_off[2];
    #pragma unroll
    for (int ks = 0; ks < 2; ks++) {
        int row = wid * 16 + (lane & 15);
        int c   = ks * 2 + (lane >> 4);
        a_off[ks] = (uint32_t)(row * 64 + (c ^ ((row >> 1) & 3)) * 16);
    }
    uint32_t b_off[2][2];
    #pragma unroll
    for (int nt = 0; nt < 2; nt++)
        #pragma unroll
        for (int ks = 0; ks < 2; ks++) {
            int k = ks * 16 + (lane & 15);
            int c = nt * 2 + (lane >> 4);
            b_off[nt][ks] = (uint32_t)(k * 64 + (c ^ ((k >> 1) & 3)) * 16);
        }

    // prologue
    cp_async16(sA_u + dA0, Ag0);
    cp_async16(sA_u + dA1, Ag1);
    cp_async16(sB_u + dB,  Bg);
    CP_COMMIT();

    const int NT = DMODEL / 32;   // 32 tiles
    int buf = 0;
    #pragma unroll 1
    for (int t = 0; t < NT; t++) {
        if (t + 1 < NT) {
            int k0g = (t + 1) * 32;
            uint32_t ab = sA_u + (buf ^ 1) * BC_ASZ;
            uint32_t bb = sB_u + (buf ^ 1) * BC_BSZ;
            cp_async16(ab + dA0, Ag0 + k0g);
            cp_async16(ab + dA1, Ag1 + k0g);
            cp_async16(bb + dB,  Bg + (size_t)k0g * 32);
            CP_COMMIT();
            CP_WAIT(1);
        } else {
            CP_WAIT(0);
        }
        __syncthreads();

        uint32_t Ab = sA_u + buf * BC_ASZ;
        uint32_t Bb = sB_u + buf * BC_BSZ;
        #pragma unroll
        for (int ks = 0; ks < 2; ks++) {
            uint32_t af[4], bf[2][4];
            ldsm_x4(af[0], af[1], af[2], af[3], Ab + a_off[ks]);
            #pragma unroll
            for (int nt = 0; nt < 2; nt++)
                ldsm_x4_t(bf[nt][0], bf[nt][1], bf[nt][2], bf[nt][3],
                          Bb + b_off[nt][ks]);
            #pragma unroll
            for (int nt = 0; nt < 2; nt++) {
                mma_f16(acc[2*nt][0],   acc[2*nt][1],
                        acc[2*nt][2],   acc[2*nt][3],
                        af[0], af[1], af[2], af[3],
                        bf[nt][0], bf[nt][1]);
                mma_f16(acc[2*nt+1][0], acc[2*nt+1][1],
                        acc[2*nt+1][2], acc[2*nt+1][3],
                        af[0], af[1], af[2], af[3],
                        bf[nt][2], bf[nt][3]);
            }
        }
        __syncthreads();
        buf ^= 1;
    }

    // epilogue: nf 0..1 -> Bm (cols 0..15), nf 2..3 -> Cm (cols 0..15)
    #pragma unroll
    for (int nf = 0; nf < 4; nf++) {
        int col = nf * 8 + tg * 2;             // 0..30
        float bv0, bv1;
        float* dst;
        int dcol;
        if (col < 16) { bv0 = bbv[col];      bv1 = bbv[col + 1];      dst = g_Bm; dcol = col; }
        else          { bv0 = bcv[col - 16]; bv1 = bcv[col - 15];     dst = g_Cm; dcol = col - 16; }
        int row0 = brow + wid * 16 + g;
        float2 o0, o1;
        o0.x = acc[nf][0] + bv0;  o0.y = acc[nf][1] + bv1;
        o1.x = acc[nf][2] + bv0;  o1.y = acc[nf][3] + bv1;
        *(float2*)&dst[(size_t)row0 * NSTATE + dcol]       = o0;
        *(float2*)&dst[(size_t)(row0 + 8) * NSTATE + dcol] = o1;
    }
}

// ---------------- kernel 3: scan phase A (2 threads per d, 8 states each) --
__global__ __launch_bounds__(256) void scan_phaseA(const float* __restrict__ X)
{
    int tid  = threadIdx.x;
    int d    = blockIdx.x * 128 + (tid >> 1);
    int half = tid & 1;
    int c    = blockIdx.y;
    int b    = blockIdx.z;

    __shared__ __align__(16) float Bsm[CLEN][NSTATE];
    {
        const float4* src = (const float4*)(g_Bm + (size_t)(b * SEQ + c * CLEN) * NSTATE);
        ((float4*)Bsm)[tid] = src[tid];
    }
    float A2r[8];
    {
        const float4* ap = (const float4*)(g_A2 + (size_t)d * NSTATE + half * 8);
        *(float4*)&A2r[0] = ap[0];
        *(float4*)&A2r[4] = ap[1];
    }
    __syncthreads();

    float P[8], E[8];
    #pragma unroll
    for (int n = 0; n < 8; n++) { P[n] = 1.0f; E[n] = 0.0f; }

    size_t xoff = (size_t)(b * SEQ + c * CLEN) * DMODEL + d;
    const float* xp = X + xoff;
    const float* dp = g_delta + xoff;

    #pragma unroll 4
    for (int t = 0; t < CLEN; t++) {
        float xv = xp[(size_t)t * DMODEL];
        float dt = dp[(size_t)t * DMODEL];
        float dx = dt * xv;
        float bl[8];
        const float4* bp = (const float4*)&Bsm[t][half * 8];
        *(float4*)&bl[0] = bp[0];
        *(float4*)&bl[4] = bp[1];
        #pragma unroll
        for (int n = 0; n < 8; n++) {
            float a = ex2(dt * A2r[n]);
            P[n] *= a;
            E[n] = fmaf(a, E[n], dx * bl[n]);
        }
    }

    size_t off = ((size_t)((b * NCHUNK + c) * DMODEL + d)) * NSTATE + half * 8;
    float4* Pp = (float4*)(g_P + off);
    float4* Ep = (float4*)(g_E + off);
    Pp[0] = *(float4*)&P[0];  Pp[1] = *(float4*)&P[4];
    Ep[0] = *(float4*)&E[0];  Ep[1] = *(float4*)&E[4];
}

// ---------------- kernel 4: scan phase B ----------------
__global__ __launch_bounds__(256) void scan_phaseB()
{
    int idx = blockIdx.x * 256 + threadIdx.x;
    int b   = idx >> 14;
    int rem = idx & 16383;
    size_t base = (size_t)b * NCHUNK * DMODEL * NSTATE + rem;
    float h = 0.0f;
    #pragma unroll
    for (int c = 0; c < NCHUNK; c++) {
        size_t off = base + (size_t)c * (DMODEL * NSTATE);
        g_hin[off] = h;
        h = fmaf(g_P[off], h, g_E[off]);
    }
}

// ---------------- kernel 5: scan phase C (2 threads per d, shfl combine) ----
__global__ __launch_bounds__(256) void scan_phaseC(
    const float* __restrict__ X, const float* __restrict__ Dskip,
    float* __restrict__ Y)
{
    int tid  = threadIdx.x;
    int d    = blockIdx.x * 128 + (tid >> 1);
    int half = tid & 1;
    int c    = blockIdx.y;
    int b    = blockIdx.z;

    __shared__ __align__(16) float Bsm[CLEN][NSTATE];
    __shared__ __align__(16) float Csm[CLEN][NSTATE];
    {
        size_t so = (size_t)(b * SEQ + c * CLEN) * NSTATE;
        ((float4*)Bsm)[tid] = ((const float4*)(g_Bm + so))[tid];
        ((float4*)Csm)[tid] = ((const float4*)(g_Cm + so))[tid];
    }
    float A2r[8];
    {
        const float4* ap = (const float4*)(g_A2 + (size_t)d * NSTATE + half * 8);
        *(float4*)&A2r[0] = ap[0];
        *(float4*)&A2r[4] = ap[1];
    }
    float h[8];
    {
        size_t off = ((size_t)((b * NCHUNK + c) * DMODEL + d)) * NSTATE + half * 8;
        const float4* hp = (const float4*)(g_hin + off);
        *(float4*)&h[0] = hp[0];
        *(float4*)&h[4] = hp[1];
    }
    float dsk = Dskip[d];
    __syncthreads();

    size_t xoff = (size_t)(b * SEQ + c * CLEN) * DMODEL + d;
    const float* xp = X + xoff;
    const float* dp = g_delta + xoff;
    float* yp = Y + xoff;

    #pragma unroll 4
    for (int t = 0; t < CLEN; t++) {
        float xv = xp[(size_t)t * DMODEL];
        float dt = dp[(size_t)t * DMODEL];
        float dx = dt * xv;
        float bl[8], cl[8];
        const float4* bp = (const float4*)&Bsm[t][half * 8];
        const float4* cp = (const float4*)&Csm[t][half * 8];
        *(float4*)&bl[0] = bp[0]; *(float4*)&bl[4] = bp[1];
        *(float4*)&cl[0] = cp[0]; *(float4*)&cl[4] = cp[1];
        float acc0 = 0.0f, acc1 = 0.0f;
        #pragma unroll
        for (int n = 0; n < 8; n += 2) {
            float a0 = ex2(dt * A2r[n]);
            float a1 = ex2(dt * A2r[n + 1]);
            h[n]     = fmaf(a0, h[n],     dx * bl[n]);
            h[n + 1] = fmaf(a1, h[n + 1], dx * bl[n + 1]);
            acc0 = fmaf(h[n],     cl[n],     acc0);
            acc1 = fmaf(h[n + 1], cl[n + 1], acc1);
        }
        float acc = acc0 + acc1;
        acc += __shfl_xor_sync(0xFFFFFFFFu, acc, 1);
        if (half == 0)
            yp[(size_t)t * DMODEL] = acc + xv * dsk;
    }
}

// ---------------- launch ----------------
extern "C" void kernel_launch(void* const* d_in, const int* in_sizes, int n_in,
                              void* d_out, int out_size)
{
    const float* x     = (const float*)d_in[0];
    const float* A_log = (const float*)d_in[1];
    const float* Dsk   = (const float*)d_in[2];
    const float* Wd    = (const float*)d_in[3];
    const float* bd    = (const float*)d_in[4];
    const float* Wb    = (const float*)d_in[5];
    const float* bb    = (const float*)d_in[6];
    const float* Wc    = (const float*)d_in[7];
    const float* bc    = (const float*)d_in[8];
    float* y = (float*)d_out;

    __half* xh_sym = nullptr;
    __half* wh_sym = nullptr;
    cudaGetSymbolAddress((void**)&xh_sym, g_Xh);
    cudaGetSymbolAddress((void**)&wh_sym, g_Wh);
    cudaFuncSetAttribute(gemm_f16_softplus,
                         cudaFuncAttributeMaxDynamicSharedMemorySize,
                         GEMM_SMEM);

    prep_A2_kernel<<<(DMODEL*NSTATE + 255) / 256, 256>>>(A_log);
    convert_f16_kernel<<<(MROWS * DMODEL / 4) / 256, 256>>>(x, xh_sym);
    convert_f16_kernel<<<(DMODEL * DMODEL / 4) / 256, 256>>>(Wd, wh_sym);
    pack_wbc_kernel<<<(DMODEL * 32) / 256, 256>>>(Wb, Wc);
    gemm_f16_softplus<<<dim3(DMODEL / GBN, MROWS / GBM), 256, GEMM_SMEM>>>(bd);
    bc_gemm<<<MROWS / BCM, 128>>>(bb, bc);
    scan_phaseA<<<dim3(DMODEL / 128, NCHUNK, B_SZ), 256>>>(x);
    scan_phaseB<<<(B_SZ * DMODEL * NSTATE) / 256, 256>>>();
    scan_phaseC<<<dim3(DMODEL / 128, NCHUNK, B_SZ), 256>>>(x, Dsk, y);
}